// round 1
// baseline (speedup 1.0000x reference)
#include <cuda_runtime.h>
#include <cuda_bf16.h>
#include <math.h>

// Problem constants
#define BB_   4        // batch
#define NC    128      // channels
#define KK    250      // chunk len
#define SS    250      // num chunks
#define MM    32       // modes
#define LL    250      // s4 seq len (K or S, both 250)
#define NBATCH 1000    // B*S == B*K
#define NCOL  250000   // NBATCH * LL
#define TOT   32000000 // B*N*K*S
#define PERB  8000000  // N*K*S (elements per batch for groupnorm)

// Scratch (static device globals; reused across stages)
__device__ float g_buf0[32000000];  // u, later linT
__device__ float g_buf1[32000000];  // yT, later gluT
__device__ float g_buf2[64000000];  // z (256 x 250000), later pre-norm (first 32M)
__device__ float g_kern[NC * LL];
__device__ double g_stats[8];

// ---------------------------------------------------------------------------
// Pack intra: u[(b*S+s)*N*K + h*K + k] = x[((b*N+h)*K + k)*S + s]
// 250x250 tile transpose per (b,h) via smem tiles.
__global__ void pack_intra(const float* __restrict__ x) {
    __shared__ float tile[32][33];
    int bh = blockIdx.y;            // 0..511
    int b = bh >> 7, h = bh & 127;
    int tk = blockIdx.x & 7;        // tile in k
    int ts = blockIdx.x >> 3;       // tile in s
    int k = tk * 32 + threadIdx.y;
    int s = ts * 32 + threadIdx.x;
    if (k < KK && s < SS)
        tile[threadIdx.y][threadIdx.x] = x[(((long)(b * NC + h) * KK + k) * SS) + s];
    __syncthreads();
    int s2 = ts * 32 + threadIdx.y;
    int k2 = tk * 32 + threadIdx.x;
    if (s2 < SS && k2 < KK)
        g_buf0[(((long)(b * SS + s2) * NC + h) * KK) + k2] = tile[threadIdx.x][threadIdx.y];
}

// Pack inter: u[((b*K+k)*N + h)*S + s] = prev[((b*N+h)*K + k)*S + s]
__global__ void pack_inter(const float* __restrict__ in) {
    long i = (long)blockIdx.x * 256 + threadIdx.x;
    if (i >= TOT) return;
    int s = (int)(i % 250);
    long t = i / 250;
    int h = (int)(t % 128); t /= 128;
    int k = (int)(t % 250);
    int b = (int)(t / 250);
    g_buf0[i] = in[(((long)(b * NC + h) * KK + k) * SS) + s];
}

// ---------------------------------------------------------------------------
// S4D kernel synthesis: kern[h,l] = 2*Re( sum_m C[h,m] * exp(dtA[h,m]*l) )
__global__ void kern_compute(const float* __restrict__ log_dt,
                             const float* __restrict__ logA_re,
                             const float* __restrict__ A_im,
                             const float* __restrict__ C_re,
                             const float* __restrict__ C_im) {
    __shared__ float sCr[MM], sCi[MM], sar[MM], sai[MM];
    int h = blockIdx.x;
    int t = threadIdx.x;
    if (t < MM) {
        float dt  = expf(log_dt[h]);
        float Are = -expf(logA_re[h * MM + t]);
        float Aim = A_im[h * MM + t];
        float ar = dt * Are, ai = dt * Aim;
        float ea = expf(ar);
        float sb, cb; sincosf(ai, &sb, &cb);
        float er = ea * cb - 1.f, ei = ea * sb;
        float den = Are * Are + Aim * Aim;
        float qr = (er * Are + ei * Aim) / den;
        float qi = (ei * Are - er * Aim) / den;
        float cr = C_re[h * MM + t], ci = C_im[h * MM + t];
        sCr[t] = cr * qr - ci * qi;
        sCi[t] = cr * qi + ci * qr;
        sar[t] = ar; sai[t] = ai;
    }
    __syncthreads();
    if (t < LL) {
        float fl = (float)t;
        float sum = 0.f;
        #pragma unroll
        for (int m = 0; m < MM; ++m) {
            float ea = expf(sar[m] * fl);
            float sb, cb; sincosf(sai[m] * fl, &sb, &cb);
            sum += ea * (sCr[m] * cb - sCi[m] * sb);
        }
        g_kern[h * LL + t] = 2.f * sum;
    }
}

// ---------------------------------------------------------------------------
// Causal conv + D*u + GELU(tanh). Reads g_buf0 [bb][h][l], writes yT = g_buf1
// as [h][bb*L + l] (transposed for the big ow GEMM).
__global__ void conv_gelu(const float* __restrict__ D) {
    __shared__ float su[512];   // zero-padded input: su[250+i] = u[i]
    __shared__ float sk[256];
    int row = blockIdx.x;       // bb*128 + h
    int bb = row >> 7, h = row & 127;
    int t = threadIdx.x;
    if (t < LL) {
        su[t] = 0.f;
        su[250 + t] = g_buf0[(long)row * LL + t];
        sk[t] = g_kern[h * LL + t];
    }
    __syncthreads();
    if (t < LL) {
        float acc = D[h] * su[250 + t];
        int wmax = min(249, t | 31);   // warp-uniform trip count
        #pragma unroll 4
        for (int j = 0; j <= wmax; ++j)
            acc += sk[j] * su[250 + t - j];
        float c = acc + 0.044715f * acc * acc * acc;
        float g = 0.5f * acc * (1.f + tanhf(0.7978845608f * c));
        g_buf1[(long)h * NCOL + bb * LL + t] = g;
    }
}

// ---------------------------------------------------------------------------
// SGEMM: C[M x 250000] = A[M x 128] @ B[128 x 250000] + bias
// MODE 0: ow GEMM (M=256), B=g_buf1 (yT), C=g_buf2 (z)
// MODE 1: lw GEMM (M=128), B=g_buf1 (gluT), C=g_buf0 (linT)
template <int MODE>
__global__ void gemm_k128(const float* __restrict__ A, const float* __restrict__ bias) {
    const float* __restrict__ Bm = g_buf1;
    float* __restrict__ C = (MODE == 0) ? g_buf2 : g_buf0;
    const int ncols = NCOL;

    __shared__ float Ast[32][128];   // [k][m]
    __shared__ float Bs[32][128];    // [k][n]

    int tid = threadIdx.x;
    int tx = tid & 15, ty = tid >> 4;
    int m0 = blockIdx.y * 128;
    long n0 = (long)blockIdx.x * 128;

    float acc[8][8];
    #pragma unroll
    for (int i = 0; i < 8; ++i)
        #pragma unroll
        for (int j = 0; j < 8; ++j) acc[i][j] = 0.f;

    for (int kc = 0; kc < 4; ++kc) {
        // A tile
        {
            int c4 = (tid & 7) * 4;
            int rb = tid >> 3;
            #pragma unroll
            for (int p = 0; p < 4; ++p) {
                int r = rb + p * 32;
                float4 v = *(const float4*)(A + (long)(m0 + r) * 128 + kc * 32 + c4);
                Ast[c4 + 0][r] = v.x; Ast[c4 + 1][r] = v.y;
                Ast[c4 + 2][r] = v.z; Ast[c4 + 3][r] = v.w;
            }
        }
        // B tile (guarded on ncols edge)
        {
            int n4 = (tid & 31) * 4;
            int kb = tid >> 5;
            #pragma unroll
            for (int p = 0; p < 4; ++p) {
                int kr = kb + p * 8;
                long col = n0 + n4;
                const float* bp = Bm + (long)(kc * 32 + kr) * ncols + col;
                float4 v;
                if (col + 4 <= ncols) v = *(const float4*)bp;
                else {
                    v.x = (col + 0 < ncols) ? bp[0] : 0.f;
                    v.y = (col + 1 < ncols) ? bp[1] : 0.f;
                    v.z = (col + 2 < ncols) ? bp[2] : 0.f;
                    v.w = (col + 3 < ncols) ? bp[3] : 0.f;
                }
                *(float4*)&Bs[kr][n4] = v;
            }
        }
        __syncthreads();
        #pragma unroll
        for (int kk = 0; kk < 32; ++kk) {
            float ra[8], rb8[8];
            *(float4*)&ra[0]  = *(const float4*)&Ast[kk][ty * 8];
            *(float4*)&ra[4]  = *(const float4*)&Ast[kk][ty * 8 + 4];
            *(float4*)&rb8[0] = *(const float4*)&Bs[kk][tx * 8];
            *(float4*)&rb8[4] = *(const float4*)&Bs[kk][tx * 8 + 4];
            #pragma unroll
            for (int i = 0; i < 8; ++i)
                #pragma unroll
                for (int j = 0; j < 8; ++j)
                    acc[i][j] += ra[i] * rb8[j];
        }
        __syncthreads();
    }
    #pragma unroll
    for (int i = 0; i < 8; ++i) {
        int row = m0 + ty * 8 + i;
        float bv = bias[row];
        #pragma unroll
        for (int j = 0; j < 8; ++j) {
            long col = n0 + tx * 8 + j;
            if (col < ncols)
                C[(long)row * ncols + col] = acc[i][j] + bv;
        }
    }
}

// ---------------------------------------------------------------------------
// GLU + scramble into the 128-chunked flatten layout used by the lw linear.
// Reads z = g_buf2 [o][col], writes gluT = g_buf1 [c][r] where
// f = o*250 + l, r = bb*250 + f/128, c = f%128.
__global__ void glu_scramble() {
    long i = (long)blockIdx.x * 256 + threadIdx.x;   // over 128 * NCOL
    if (i >= (long)NC * NCOL) return;
    int col = (int)(i % NCOL);
    int o = (int)(i / NCOL);
    float z1 = g_buf2[(long)o * NCOL + col];
    float z2 = g_buf2[(long)(o + 128) * NCOL + col];
    float g = z1 / (1.f + expf(-z2));
    int bb = col / 250, l = col % 250;
    int f = o * 250 + l;
    g_buf1[(long)(f & 127) * NCOL + bb * 250 + (f >> 7)] = g;
}

__global__ void zero_stats() {
    if (threadIdx.x < 8) g_stats[threadIdx.x] = 0.0;
}

// ---------------------------------------------------------------------------
// Unscramble linT -> pre[b][h][k][s] and accumulate groupnorm stats.
// mode 0 (intra): bb = b*250 + s, f = h*250 + k
// mode 1 (inter): bb = b*250 + k, f = h*250 + s
__global__ void unscramble_stats(int mode) {
    int i = blockIdx.x * 256 + threadIdx.x;
    int s = i % 250;
    int t = i / 250;
    int k = t % 250; t /= 250;
    int h = t & 127;
    int b = t >> 7;
    int u_ = (mode == 0) ? s : k;
    int v_ = (mode == 0) ? k : s;
    int bb = b * 250 + u_;
    int f  = h * 250 + v_;
    float val = g_buf0[(long)(f & 127) * NCOL + bb * 250 + (f >> 7)];
    g_buf2[i] = val;

    // block reduction of sum and sumsq (block spans a single batch b: 8M % 256 == 0)
    float sum = val, sq = val * val;
    #pragma unroll
    for (int off = 16; off; off >>= 1) {
        sum += __shfl_down_sync(0xffffffffu, sum, off);
        sq  += __shfl_down_sync(0xffffffffu, sq, off);
    }
    __shared__ float ssum[8], ssq[8];
    int lane = threadIdx.x & 31, w = threadIdx.x >> 5;
    if (lane == 0) { ssum[w] = sum; ssq[w] = sq; }
    __syncthreads();
    if (threadIdx.x == 0) {
        float ts_ = 0.f, tq = 0.f;
        #pragma unroll
        for (int j = 0; j < 8; ++j) { ts_ += ssum[j]; tq += ssq[j]; }
        atomicAdd(&g_stats[2 * b], (double)ts_);
        atomicAdd(&g_stats[2 * b + 1], (double)tq);
    }
}

// GroupNorm apply + residual. pre = g_buf2.
__global__ void norm_kernel(const float* __restrict__ gg, const float* __restrict__ gb,
                            const float* __restrict__ resid, float* __restrict__ out) {
    int i = blockIdx.x * 256 + threadIdx.x;
    int h = (i / 62500) & 127;
    int b = i / PERB;
    double mu  = g_stats[2 * b] / (double)PERB;
    double var = g_stats[2 * b + 1] / (double)PERB - mu * mu;
    float inv = (float)(1.0 / sqrt(var + 1e-8));
    out[i] = (g_buf2[i] - (float)mu) * inv * gg[h] + gb[h] + resid[i];
}

// ---------------------------------------------------------------------------
extern "C" void kernel_launch(void* const* d_in, const int* in_sizes, int n_in,
                              void* d_out, int out_size) {
    const float* x = (const float*)d_in[0];
    const float* ip[12];
    const float* pp[12];
    for (int j = 0; j < 12; ++j) ip[j] = (const float*)d_in[1 + j];
    for (int j = 0; j < 12; ++j) pp[j] = (const float*)d_in[13 + j];
    float* out = (float*)d_out;

    const int EB = TOT / 256;              // 125000 elementwise blocks
    dim3 packGrid(64, 512), packBlk(32, 32);

    // ---- intra path (L = K) ----
    pack_intra<<<packGrid, packBlk>>>(x);
    kern_compute<<<NC, 256>>>(ip[0], ip[1], ip[2], ip[3], ip[4]);
    conv_gelu<<<NBATCH * NC, 256>>>(ip[5]);
    gemm_k128<0><<<dim3(1954, 2), 256>>>(ip[6], ip[7]);   // ow, ob
    glu_scramble<<<EB, 256>>>();
    gemm_k128<1><<<dim3(1954, 1), 256>>>(ip[8], ip[9]);   // lw, lb
    zero_stats<<<1, 32>>>();
    unscramble_stats<<<EB, 256>>>(0);
    norm_kernel<<<EB, 256>>>(ip[10], ip[11], x, out);     // out = intra_final

    // ---- inter path (L = S) ----
    pack_inter<<<EB, 256>>>(out);
    kern_compute<<<NC, 256>>>(pp[0], pp[1], pp[2], pp[3], pp[4]);
    conv_gelu<<<NBATCH * NC, 256>>>(pp[5]);
    gemm_k128<0><<<dim3(1954, 2), 256>>>(pp[6], pp[7]);
    glu_scramble<<<EB, 256>>>();
    gemm_k128<1><<<dim3(1954, 1), 256>>>(pp[8], pp[9]);
    zero_stats<<<1, 32>>>();
    unscramble_stats<<<EB, 256>>>(1);
    norm_kernel<<<EB, 256>>>(pp[10], pp[11], out, out);   // out = inter_norm + intra_final
}

// round 2
// speedup vs baseline: 1.1386x; 1.1386x over previous
#include <cuda_runtime.h>
#include <math.h>

#define NC    128
#define LL    250
#define MM    32
#define NCOL  250000
#define TOT   32000000
#define PERB  8000000

// Scratch
__device__ float g_buf0[32000000];  // u -> G (glu out, natural flat) -> u_inter
__device__ float g_buf1[32000000];  // yT -> Lf (lw out, flat)
__device__ float g_buf2[64000000];  // z (256 x 250000) -> pre-norm (first 32M)
__device__ float g_kern[NC * LL];
__device__ double g_stats[8];

// ---------------------------------------------------------------------------
// f32x2 packed-FMA helpers (sm_100+ PTX)
typedef unsigned long long u64;
__device__ __forceinline__ u64 dup2(float x) {
    u64 r; asm("mov.b64 %0,{%1,%1};" : "=l"(r) : "f"(x)); return r;
}
__device__ __forceinline__ u64 pk2(float x, float y) {
    u64 r; asm("mov.b64 %0,{%1,%2};" : "=l"(r) : "f"(x), "f"(y)); return r;
}
__device__ __forceinline__ void fma2(u64& a, u64 b, u64 c) {
    asm("fma.rn.f32x2 %0,%1,%2,%0;" : "+l"(a) : "l"(b), "l"(c));
}
__device__ __forceinline__ void un2(u64 v, float& x, float& y) {
    asm("mov.b64 {%0,%1},%2;" : "=f"(x), "=f"(y) : "l"(v));
}

// ---------------------------------------------------------------------------
// Pack intra: u[(b*250+s)*128*250 + h*250 + k] = x[((b*128+h)*250 + k)*250 + s]
__global__ void pack_intra(const float* __restrict__ x) {
    __shared__ float tile[32][33];
    int bh = blockIdx.y;            // b*128 + h
    int b = bh >> 7, h = bh & 127;
    int tk = blockIdx.x & 7;
    int ts = blockIdx.x >> 3;
    int k = tk * 32 + threadIdx.y;
    int s = ts * 32 + threadIdx.x;
    if (k < 250 && s < 250)
        tile[threadIdx.y][threadIdx.x] = x[(((long)bh * 250 + k) * 250) + s];
    __syncthreads();
    int s2 = ts * 32 + threadIdx.y;
    int k2 = tk * 32 + threadIdx.x;
    if (s2 < 250 && k2 < 250)
        g_buf0[(((long)(b * 250 + s2) * 128 + h) * 250) + k2] = tile[threadIdx.x][threadIdx.y];
}

// ---------------------------------------------------------------------------
// S4D kernel synthesis
__global__ void kern_compute(const float* __restrict__ log_dt,
                             const float* __restrict__ logA_re,
                             const float* __restrict__ A_im,
                             const float* __restrict__ C_re,
                             const float* __restrict__ C_im) {
    __shared__ float sCr[MM], sCi[MM], sar[MM], sai[MM];
    int h = blockIdx.x;
    int t = threadIdx.x;
    if (t < MM) {
        float dt  = expf(log_dt[h]);
        float Are = -expf(logA_re[h * MM + t]);
        float Aim = A_im[h * MM + t];
        float ar = dt * Are, ai = dt * Aim;
        float ea = expf(ar);
        float sb, cb; sincosf(ai, &sb, &cb);
        float er = ea * cb - 1.f, ei = ea * sb;
        float den = Are * Are + Aim * Aim;
        float qr = (er * Are + ei * Aim) / den;
        float qi = (ei * Are - er * Aim) / den;
        float cr = C_re[h * MM + t], ci = C_im[h * MM + t];
        sCr[t] = cr * qr - ci * qi;
        sCi[t] = cr * qi + ci * qr;
        sar[t] = ar; sai[t] = ai;
    }
    __syncthreads();
    if (t < LL) {
        float fl = (float)t;
        float sum = 0.f;
        #pragma unroll
        for (int m = 0; m < MM; ++m) {
            float ea = expf(sar[m] * fl);
            float sb, cb; sincosf(sai[m] * fl, &sb, &cb);
            sum += ea * (sCr[m] * cb - sCi[m] * sb);
        }
        g_kern[h * LL + t] = 2.f * sum;
    }
}

// ---------------------------------------------------------------------------
// Causal conv + D*u + GELU, register-blocked, f32x2.
// Warp per row (bb,h); thread computes 8 contiguous outputs.
// Reads g_buf0 [bb][h][l]; writes yT = g_buf1 [h][bb*250 + l].
__global__ void conv_gelu2(const float* __restrict__ D) {
    __shared__ float su[8][272];   // [warp][8 zero-pad + 250 u + tail pad]
    __shared__ float sk[8][256];   // kern (zero-padded to 256)
    int w = threadIdx.x >> 5, lane = threadIdx.x & 31;
    int h = blockIdx.x * 8 + w;
    int bb = blockIdx.y;
    long base = ((long)bb * 128 + h) * 250;

    if (lane < 8)  su[w][lane] = 0.f;
    if (lane < 16) su[w][256 + lane] = 0.f;
    for (int t = lane; t < 250; t += 32) su[w][8 + t] = g_buf0[base + t];
    for (int t = lane; t < 256; t += 32) sk[w][t] = (t < 250) ? g_kern[h * 250 + t] : 0.f;
    __syncwarp();

    int p0 = lane * 8;
    u64 acc[4];
    acc[0] = acc[1] = acc[2] = acc[3] = 0ull;

    for (int jb = 0; jb <= p0; jb += 8) {
        float4 k0 = *(const float4*)&sk[w][jb];
        float4 k1 = *(const float4*)&sk[w][jb + 4];
        const float* up = &su[w][p0 - jb];   // 32B-aligned
        float4 ua = *(const float4*)(up + 0);
        float4 ub = *(const float4*)(up + 4);
        float4 uc = *(const float4*)(up + 8);
        float4 ud = *(const float4*)(up + 12);
        float uu[16] = {ua.x, ua.y, ua.z, ua.w, ub.x, ub.y, ub.z, ub.w,
                        uc.x, uc.y, uc.z, uc.w, ud.x, ud.y, ud.z, ud.w};
        u64 pr[15];
        #pragma unroll
        for (int t = 1; t < 15; ++t) pr[t] = pk2(uu[t], uu[t + 1]);
        float kk[8] = {k0.x, k0.y, k0.z, k0.w, k1.x, k1.y, k1.z, k1.w};
        #pragma unroll
        for (int e = 0; e < 8; ++e) {
            u64 kd = dup2(kk[e]);
            fma2(acc[0], kd, pr[8 - e]);
            fma2(acc[1], kd, pr[10 - e]);
            fma2(acc[2], kd, pr[12 - e]);
            fma2(acc[3], kd, pr[14 - e]);
        }
    }
    __syncwarp();
    float dh = D[h];
    float ys[8];
    #pragma unroll
    for (int i2 = 0; i2 < 4; ++i2) un2(acc[i2], ys[2 * i2], ys[2 * i2 + 1]);
    #pragma unroll
    for (int i = 0; i < 8; ++i) {
        float v = ys[i] + dh * su[w][8 + p0 + i];
        float c = v + 0.044715f * v * v * v;
        ys[i] = 0.5f * v * (1.f + tanhf(0.7978845608f * c));
    }
    __syncwarp();
    #pragma unroll
    for (int i = 0; i < 8; ++i) su[w][8 + p0 + i] = ys[i];
    __syncwarp();
    long obase = (long)h * NCOL + (long)bb * 250;
    for (int t = lane; t < 250; t += 32) g_buf1[obase + t] = su[w][8 + t];
}

// ---------------------------------------------------------------------------
// GEMM1 (ow): C[256 x 250000] = ow[256x128] @ yT[128 x 250000] + ob
__global__ void gemm_ow(const float* __restrict__ A, const float* __restrict__ bias) {
    const float* __restrict__ Bm = g_buf1;
    float* __restrict__ C = g_buf2;
    __shared__ float Ast[32][128];   // [k][m]
    __shared__ float Bs[32][128];    // [k][n]

    int tid = threadIdx.x;
    int tx = tid & 15, ty = tid >> 4;
    int m0 = blockIdx.y * 128;
    long n0 = (long)blockIdx.x * 128;

    u64 acc[8][4];
    #pragma unroll
    for (int i = 0; i < 8; ++i)
        #pragma unroll
        for (int j = 0; j < 4; ++j) acc[i][j] = 0ull;

    for (int kc = 0; kc < 4; ++kc) {
        {
            int c4 = (tid & 7) * 4;
            int rb = tid >> 3;
            #pragma unroll
            for (int p = 0; p < 4; ++p) {
                int r = rb + p * 32;
                float4 v = *(const float4*)(A + (long)(m0 + r) * 128 + kc * 32 + c4);
                Ast[c4 + 0][r] = v.x; Ast[c4 + 1][r] = v.y;
                Ast[c4 + 2][r] = v.z; Ast[c4 + 3][r] = v.w;
            }
        }
        {
            int n4 = (tid & 31) * 4;
            int kb = tid >> 5;
            #pragma unroll
            for (int p = 0; p < 4; ++p) {
                int kr = kb + p * 8;
                long col = n0 + n4;
                const float* bp = Bm + (long)(kc * 32 + kr) * NCOL + col;
                float4 v;
                if (col + 4 <= NCOL) v = *(const float4*)bp;
                else {
                    v.x = (col + 0 < NCOL) ? bp[0] : 0.f;
                    v.y = (col + 1 < NCOL) ? bp[1] : 0.f;
                    v.z = (col + 2 < NCOL) ? bp[2] : 0.f;
                    v.w = (col + 3 < NCOL) ? bp[3] : 0.f;
                }
                *(float4*)&Bs[kr][n4] = v;
            }
        }
        __syncthreads();
        #pragma unroll
        for (int kk = 0; kk < 32; ++kk) {
            float4 a0 = *(const float4*)&Ast[kk][ty * 8];
            float4 a1 = *(const float4*)&Ast[kk][ty * 8 + 4];
            float4 b0 = *(const float4*)&Bs[kk][tx * 8];
            float4 b1 = *(const float4*)&Bs[kk][tx * 8 + 4];
            u64 ad[8] = {dup2(a0.x), dup2(a0.y), dup2(a0.z), dup2(a0.w),
                         dup2(a1.x), dup2(a1.y), dup2(a1.z), dup2(a1.w)};
            u64 bp4[4] = {pk2(b0.x, b0.y), pk2(b0.z, b0.w),
                          pk2(b1.x, b1.y), pk2(b1.z, b1.w)};
            #pragma unroll
            for (int i = 0; i < 8; ++i)
                #pragma unroll
                for (int j = 0; j < 4; ++j)
                    fma2(acc[i][j], ad[i], bp4[j]);
        }
        __syncthreads();
    }
    #pragma unroll
    for (int i = 0; i < 8; ++i) {
        int row = m0 + ty * 8 + i;
        float bv = bias[row];
        float c[8];
        #pragma unroll
        for (int j = 0; j < 4; ++j) un2(acc[i][j], c[2 * j], c[2 * j + 1]);
        long col = n0 + tx * 8;
        float* cp = C + (long)row * NCOL + col;
        if (col + 8 <= NCOL) {
            float4 v0 = {c[0] + bv, c[1] + bv, c[2] + bv, c[3] + bv};
            float4 v1 = {c[4] + bv, c[5] + bv, c[6] + bv, c[7] + bv};
            *(float4*)(cp) = v0;
            *(float4*)(cp + 4) = v1;
        } else {
            #pragma unroll
            for (int j = 0; j < 8; ++j)
                if (col + j < NCOL) cp[j] = c[j] + bv;
        }
    }
}

// ---------------------------------------------------------------------------
// GLU: z -> G in natural flat layout [bb][o][l] (all coalesced)
__global__ void glu_k() {
    long i = (long)blockIdx.x * 256 + threadIdx.x;   // 32M
    float z1 = g_buf2[i];
    float z2 = g_buf2[i + 32000000];
    float g = z1 / (1.f + expf(-z2));
    int col = (int)(i % NCOL);
    int o = (int)(i / NCOL);
    int bb = col / 250, l = col % 250;
    g_buf0[((long)bb * 128 + o) * 250 + l] = g;
}

// ---------------------------------------------------------------------------
// GEMM2 (lw) on flat rows: C[r][c] = sum_k G[r][k] * W[c][k] + lb[c]
// G = g_buf0 (250000 x 128 row-major), C = g_buf1 (same shape)
__global__ void gemm_lw(const float* __restrict__ W, const float* __restrict__ bias) {
    const float* __restrict__ G = g_buf0;
    float* __restrict__ C = g_buf1;
    __shared__ float Gs[32][128];   // [k][r]
    __shared__ float Ws[32][128];   // [k][c]

    int tid = threadIdx.x;
    int tx = tid & 15, ty = tid >> 4;
    long r0 = (long)blockIdx.x * 128;

    u64 acc[8][4];
    #pragma unroll
    for (int i = 0; i < 8; ++i)
        #pragma unroll
        for (int j = 0; j < 4; ++j) acc[i][j] = 0ull;

    for (int kc = 0; kc < 4; ++kc) {
        int c4 = (tid & 7) * 4;
        int rb = tid >> 3;
        #pragma unroll
        for (int p = 0; p < 4; ++p) {
            int r = rb + p * 32;
            long grow = r0 + r;
            if (grow >= NCOL) grow = NCOL - 1;   // clamp; stores guarded
            float4 v = *(const float4*)(G + grow * 128 + kc * 32 + c4);
            Gs[c4 + 0][r] = v.x; Gs[c4 + 1][r] = v.y;
            Gs[c4 + 2][r] = v.z; Gs[c4 + 3][r] = v.w;
            float4 wv = *(const float4*)(W + (long)r * 128 + kc * 32 + c4);
            Ws[c4 + 0][r] = wv.x; Ws[c4 + 1][r] = wv.y;
            Ws[c4 + 2][r] = wv.z; Ws[c4 + 3][r] = wv.w;
        }
        __syncthreads();
        #pragma unroll
        for (int kk = 0; kk < 32; ++kk) {
            float4 a0 = *(const float4*)&Gs[kk][ty * 8];
            float4 a1 = *(const float4*)&Gs[kk][ty * 8 + 4];
            float4 b0 = *(const float4*)&Ws[kk][tx * 8];
            float4 b1 = *(const float4*)&Ws[kk][tx * 8 + 4];
            u64 ad[8] = {dup2(a0.x), dup2(a0.y), dup2(a0.z), dup2(a0.w),
                         dup2(a1.x), dup2(a1.y), dup2(a1.z), dup2(a1.w)};
            u64 bp4[4] = {pk2(b0.x, b0.y), pk2(b0.z, b0.w),
                          pk2(b1.x, b1.y), pk2(b1.z, b1.w)};
            #pragma unroll
            for (int i = 0; i < 8; ++i)
                #pragma unroll
                for (int j = 0; j < 4; ++j)
                    fma2(acc[i][j], ad[i], bp4[j]);
        }
        __syncthreads();
    }
    // bias per COLUMN c
    float bb0[8];
    {
        float4 b0 = *(const float4*)(bias + tx * 8);
        float4 b1 = *(const float4*)(bias + tx * 8 + 4);
        bb0[0] = b0.x; bb0[1] = b0.y; bb0[2] = b0.z; bb0[3] = b0.w;
        bb0[4] = b1.x; bb0[5] = b1.y; bb0[6] = b1.z; bb0[7] = b1.w;
    }
    #pragma unroll
    for (int i = 0; i < 8; ++i) {
        long row = r0 + ty * 8 + i;
        if (row >= NCOL) continue;
        float c[8];
        #pragma unroll
        for (int j = 0; j < 4; ++j) un2(acc[i][j], c[2 * j], c[2 * j + 1]);
        float4 v0 = {c[0] + bb0[0], c[1] + bb0[1], c[2] + bb0[2], c[3] + bb0[3]};
        float4 v1 = {c[4] + bb0[4], c[5] + bb0[5], c[6] + bb0[6], c[7] + bb0[7]};
        float* cp = C + row * 128 + tx * 8;
        *(float4*)(cp) = v0;
        *(float4*)(cp + 4) = v1;
    }
}

// ---------------------------------------------------------------------------
__global__ void zero_stats() {
    if (threadIdx.x < 8) g_stats[threadIdx.x] = 0.0;
}

// intra: pre[b][n][k][s] = Lf[(b*250+s)*32000 + n*250 + k]; tiled transpose + stats
__global__ void trans_stats_intra() {
    __shared__ float tile[32][33];
    __shared__ float rs[32], rq[32];
    int bn = blockIdx.y;             // b*128 + n
    int b = bn >> 7, n = bn & 127;
    int tk = blockIdx.x & 7, ts = blockIdx.x >> 3;
    int s = ts * 32 + threadIdx.y;
    int k = tk * 32 + threadIdx.x;
    float v = 0.f;
    if (s < 250 && k < 250)
        v = g_buf1[((long)(b * 250 + s)) * 32000 + n * 250 + k];
    tile[threadIdx.y][threadIdx.x] = v;
    __syncthreads();
    int k2 = tk * 32 + threadIdx.y;
    int s2 = ts * 32 + threadIdx.x;
    float wv = tile[threadIdx.x][threadIdx.y];
    bool ok = (k2 < 250 && s2 < 250);
    if (ok)
        g_buf2[(((long)bn * 250 + k2) * 250) + s2] = wv;
    float sum = ok ? wv : 0.f;
    float sq = sum * sum;
    #pragma unroll
    for (int off = 16; off; off >>= 1) {
        sum += __shfl_down_sync(0xffffffffu, sum, off);
        sq  += __shfl_down_sync(0xffffffffu, sq, off);
    }
    if (threadIdx.x == 0) { rs[threadIdx.y] = sum; rq[threadIdx.y] = sq; }
    __syncthreads();
    if (threadIdx.y == 0) {
        float a = rs[threadIdx.x], q = rq[threadIdx.x];
        #pragma unroll
        for (int off = 16; off; off >>= 1) {
            a += __shfl_down_sync(0xffffffffu, a, off);
            q += __shfl_down_sync(0xffffffffu, q, off);
        }
        if (threadIdx.x == 0) {
            atomicAdd(&g_stats[2 * b], (double)a);
            atomicAdd(&g_stats[2 * b + 1], (double)q);
        }
    }
}

// inter: pre[b][n][k][s] = Lf[(b*250+k)*32000 + n*250 + s]; coalesced copy + stats
__global__ void copy_stats_inter() {
    int i = blockIdx.x * 256 + threadIdx.x;
    int s = i % 250;
    int t = i / 250;
    int k = t % 250; t /= 250;
    int n = t & 127;
    int b = t >> 7;
    float v = g_buf1[((long)(b * 250 + k)) * 32000 + n * 250 + s];
    g_buf2[i] = v;
    float sum = v, sq = v * v;
    #pragma unroll
    for (int off = 16; off; off >>= 1) {
        sum += __shfl_down_sync(0xffffffffu, sum, off);
        sq  += __shfl_down_sync(0xffffffffu, sq, off);
    }
    __shared__ float ssum[8], ssq[8];
    int lane = threadIdx.x & 31, w = threadIdx.x >> 5;
    if (lane == 0) { ssum[w] = sum; ssq[w] = sq; }
    __syncthreads();
    if (threadIdx.x == 0) {
        float a = 0.f, q = 0.f;
        #pragma unroll
        for (int j = 0; j < 8; ++j) { a += ssum[j]; q += ssq[j]; }
        atomicAdd(&g_stats[2 * b], (double)a);
        atomicAdd(&g_stats[2 * b + 1], (double)q);
    }
}

// GroupNorm apply + residual; intra version also emits inter-path u (fused pack)
__global__ void norm_intra(const float* __restrict__ gg, const float* __restrict__ gb,
                           const float* __restrict__ x, float* __restrict__ out) {
    int i = blockIdx.x * 256 + threadIdx.x;
    int s = i % 250;
    int t = i / 250;
    int k = t % 250; t /= 250;
    int n = t & 127;
    int b = t >> 7;
    double mu  = g_stats[2 * b] / (double)PERB;
    double var = g_stats[2 * b + 1] / (double)PERB - mu * mu;
    float inv = (float)(1.0 / sqrt(var + 1e-8));
    float val = (g_buf2[i] - (float)mu) * inv * gg[n] + gb[n] + x[i];
    out[i] = val;
    // inter-path conv input: u[(b*250+k)*128 + n][s]
    g_buf0[(((long)(b * 250 + k)) * 128 + n) * 250 + s] = val;
}

__global__ void norm_final(const float* __restrict__ gg, const float* __restrict__ gb,
                           float* __restrict__ out) {
    int i = blockIdx.x * 256 + threadIdx.x;
    int n = (i / 62500) & 127;
    int b = i / PERB;
    double mu  = g_stats[2 * b] / (double)PERB;
    double var = g_stats[2 * b + 1] / (double)PERB - mu * mu;
    float inv = (float)(1.0 / sqrt(var + 1e-8));
    out[i] = (g_buf2[i] - (float)mu) * inv * gg[n] + gb[n] + out[i];
}

// ---------------------------------------------------------------------------
extern "C" void kernel_launch(void* const* d_in, const int* in_sizes, int n_in,
                              void* d_out, int out_size) {
    const float* x = (const float*)d_in[0];
    const float* ip[12];
    const float* pp[12];
    for (int j = 0; j < 12; ++j) ip[j] = (const float*)d_in[1 + j];
    for (int j = 0; j < 12; ++j) pp[j] = (const float*)d_in[13 + j];
    float* out = (float*)d_out;

    const int EB = TOT / 256;   // 125000

    // ---- intra path ----
    pack_intra<<<dim3(64, 512), dim3(32, 32)>>>(x);
    kern_compute<<<NC, 256>>>(ip[0], ip[1], ip[2], ip[3], ip[4]);
    conv_gelu2<<<dim3(16, 1000), 256>>>(ip[5]);
    gemm_ow<<<dim3(1954, 2), 256>>>(ip[6], ip[7]);
    glu_k<<<EB, 256>>>();
    gemm_lw<<<1954, 256>>>(ip[8], ip[9]);
    zero_stats<<<1, 32>>>();
    trans_stats_intra<<<dim3(64, 512), dim3(32, 32)>>>();
    norm_intra<<<EB, 256>>>(ip[10], ip[11], x, out);

    // ---- inter path ----
    kern_compute<<<NC, 256>>>(pp[0], pp[1], pp[2], pp[3], pp[4]);
    conv_gelu2<<<dim3(16, 1000), 256>>>(pp[5]);
    gemm_ow<<<dim3(1954, 2), 256>>>(pp[6], pp[7]);
    glu_k<<<EB, 256>>>();
    gemm_lw<<<1954, 256>>>(pp[8], pp[9]);
    zero_stats<<<1, 32>>>();
    copy_stats_inter<<<EB, 256>>>();
    norm_final<<<EB, 256>>>(pp[10], pp[11], out);
}

// round 3
// speedup vs baseline: 1.2491x; 1.0970x over previous
#include <cuda_runtime.h>
#include <math.h>

#define NC    128
#define LL    250
#define MM    32
#define NCOL  250000
#define TOT   32000000
#define PERB  8000000

// Scratch
__device__ float g_buf0[32000000];  // u -> G (glu out, natural flat) -> u_inter
__device__ float g_buf1[32000000];  // yT -> Lf (lw out, flat)
__device__ float g_buf2[32000000];  // pre-norm
__device__ float g_kern[NC * LL];
__device__ double g_stats[8];

// ---------------------------------------------------------------------------
// f32x2 packed-FMA helpers (sm_100+ PTX)
typedef unsigned long long u64;
__device__ __forceinline__ u64 dup2(float x) {
    u64 r; asm("mov.b64 %0,{%1,%1};" : "=l"(r) : "f"(x)); return r;
}
__device__ __forceinline__ u64 pk2(float x, float y) {
    u64 r; asm("mov.b64 %0,{%1,%2};" : "=l"(r) : "f"(x), "f"(y)); return r;
}
__device__ __forceinline__ void fma2(u64& a, u64 b, u64 c) {
    asm("fma.rn.f32x2 %0,%1,%2,%0;" : "+l"(a) : "l"(b), "l"(c));
}
__device__ __forceinline__ void un2(u64 v, float& x, float& y) {
    asm("mov.b64 {%0,%1},%2;" : "=f"(x), "=f"(y) : "l"(v));
}

// ---------------------------------------------------------------------------
// Pack intra: u[(b*250+s)*128*250 + h*250 + k] = x[((b*128+h)*250 + k)*250 + s]
__global__ void pack_intra(const float* __restrict__ x) {
    __shared__ float tile[32][33];
    int bh = blockIdx.y;            // b*128 + h
    int b = bh >> 7, h = bh & 127;
    int tk = blockIdx.x & 7;
    int ts = blockIdx.x >> 3;
    int k = tk * 32 + threadIdx.y;
    int s = ts * 32 + threadIdx.x;
    if (k < 250 && s < 250)
        tile[threadIdx.y][threadIdx.x] = x[(((long)bh * 250 + k) * 250) + s];
    __syncthreads();
    int s2 = ts * 32 + threadIdx.y;
    int k2 = tk * 32 + threadIdx.x;
    if (s2 < 250 && k2 < 250)
        g_buf0[(((long)(b * 250 + s2) * 128 + h) * 250) + k2] = tile[threadIdx.x][threadIdx.y];
}

// ---------------------------------------------------------------------------
// S4D kernel synthesis
__global__ void kern_compute(const float* __restrict__ log_dt,
                             const float* __restrict__ logA_re,
                             const float* __restrict__ A_im,
                             const float* __restrict__ C_re,
                             const float* __restrict__ C_im) {
    __shared__ float sCr[MM], sCi[MM], sar[MM], sai[MM];
    int h = blockIdx.x;
    int t = threadIdx.x;
    if (t < MM) {
        float dt  = expf(log_dt[h]);
        float Are = -expf(logA_re[h * MM + t]);
        float Aim = A_im[h * MM + t];
        float ar = dt * Are, ai = dt * Aim;
        float ea = expf(ar);
        float sb, cb; sincosf(ai, &sb, &cb);
        float er = ea * cb - 1.f, ei = ea * sb;
        float den = Are * Are + Aim * Aim;
        float qr = (er * Are + ei * Aim) / den;
        float qi = (ei * Are - er * Aim) / den;
        float cr = C_re[h * MM + t], ci = C_im[h * MM + t];
        sCr[t] = cr * qr - ci * qi;
        sCi[t] = cr * qi + ci * qr;
        sar[t] = ar; sai[t] = ai;
    }
    __syncthreads();
    if (t < LL) {
        float fl = (float)t;
        float sum = 0.f;
        #pragma unroll
        for (int m = 0; m < MM; ++m) {
            float ea = expf(sar[m] * fl);
            float sb, cb; sincosf(sai[m] * fl, &sb, &cb);
            sum += ea * (sCr[m] * cb - sCi[m] * sb);
        }
        g_kern[h * LL + t] = 2.f * sum;
    }
}

// ---------------------------------------------------------------------------
// Causal conv + D*u + GELU, register-blocked, f32x2.
__global__ void conv_gelu2(const float* __restrict__ D) {
    __shared__ float su[8][272];
    __shared__ float sk[8][256];
    int w = threadIdx.x >> 5, lane = threadIdx.x & 31;
    int h = blockIdx.x * 8 + w;
    int bb = blockIdx.y;
    long base = ((long)bb * 128 + h) * 250;

    if (lane < 8)  su[w][lane] = 0.f;
    if (lane < 16) su[w][256 + lane] = 0.f;
    for (int t = lane; t < 250; t += 32) su[w][8 + t] = g_buf0[base + t];
    for (int t = lane; t < 256; t += 32) sk[w][t] = (t < 250) ? g_kern[h * 250 + t] : 0.f;
    __syncwarp();

    int p0 = lane * 8;
    u64 acc[4];
    acc[0] = acc[1] = acc[2] = acc[3] = 0ull;

    for (int jb = 0; jb <= p0; jb += 8) {
        float4 k0 = *(const float4*)&sk[w][jb];
        float4 k1 = *(const float4*)&sk[w][jb + 4];
        const float* up = &su[w][p0 - jb];
        float4 ua = *(const float4*)(up + 0);
        float4 ub = *(const float4*)(up + 4);
        float4 uc = *(const float4*)(up + 8);
        float4 ud = *(const float4*)(up + 12);
        float uu[16] = {ua.x, ua.y, ua.z, ua.w, ub.x, ub.y, ub.z, ub.w,
                        uc.x, uc.y, uc.z, uc.w, ud.x, ud.y, ud.z, ud.w};
        u64 pr[15];
        #pragma unroll
        for (int t = 1; t < 15; ++t) pr[t] = pk2(uu[t], uu[t + 1]);
        float kk[8] = {k0.x, k0.y, k0.z, k0.w, k1.x, k1.y, k1.z, k1.w};
        #pragma unroll
        for (int e = 0; e < 8; ++e) {
            u64 kd = dup2(kk[e]);
            fma2(acc[0], kd, pr[8 - e]);
            fma2(acc[1], kd, pr[10 - e]);
            fma2(acc[2], kd, pr[12 - e]);
            fma2(acc[3], kd, pr[14 - e]);
        }
    }
    __syncwarp();
    float dh = D[h];
    float ys[8];
    #pragma unroll
    for (int i2 = 0; i2 < 4; ++i2) un2(acc[i2], ys[2 * i2], ys[2 * i2 + 1]);
    #pragma unroll
    for (int i = 0; i < 8; ++i) {
        float v = ys[i] + dh * su[w][8 + p0 + i];
        float c = v + 0.044715f * v * v * v;
        ys[i] = 0.5f * v * (1.f + tanhf(0.7978845608f * c));
    }
    __syncwarp();
    #pragma unroll
    for (int i = 0; i < 8; ++i) su[w][8 + p0 + i] = ys[i];
    __syncwarp();
    long obase = (long)h * NCOL + (long)bb * 250;
    for (int t = lane; t < 250; t += 32) g_buf1[obase + t] = su[w][8 + t];
}

// ---------------------------------------------------------------------------
// Fused ow GEMM + GLU.
// z[256 x NCOL] = ow[256x128] @ yT[128 x NCOL] + ob computed in two row-phases
// per block; phase 0 (rows 0..127) stashed in smem; phase 1 (rows 128..255)
// applies GLU in the epilogue and writes G directly in natural flat layout.
#define PITCH 132
__global__ void __launch_bounds__(256, 2)
gemm_ow_glu(const float* __restrict__ A, const float* __restrict__ bias) {
    extern __shared__ float sm[];
    float* As = sm;                    // [32][PITCH]
    float* Bs = sm + 32 * PITCH;       // [32][PITCH]
    float* Zs = sm + 64 * PITCH;       // [128][PITCH]
    const float* __restrict__ Bm = g_buf1;

    int tid = threadIdx.x;
    int tx = tid & 15, ty = tid >> 4;
    long n0 = (long)blockIdx.x * 128;

    for (int phase = 0; phase < 2; ++phase) {
        int m0 = phase * 128;
        u64 acc[8][4];
        #pragma unroll
        for (int i = 0; i < 8; ++i)
            #pragma unroll
            for (int j = 0; j < 4; ++j) acc[i][j] = 0ull;

        for (int kc = 0; kc < 4; ++kc) {
            {
                int c4 = (tid & 7) * 4;
                int rb = tid >> 3;
                #pragma unroll
                for (int p = 0; p < 4; ++p) {
                    int r = rb + p * 32;
                    float4 v = *(const float4*)(A + (long)(m0 + r) * 128 + kc * 32 + c4);
                    As[(c4 + 0) * PITCH + r] = v.x; As[(c4 + 1) * PITCH + r] = v.y;
                    As[(c4 + 2) * PITCH + r] = v.z; As[(c4 + 3) * PITCH + r] = v.w;
                }
            }
            {
                int n4 = (tid & 31) * 4;
                int kb = tid >> 5;
                #pragma unroll
                for (int p = 0; p < 4; ++p) {
                    int kr = kb + p * 8;
                    long col = n0 + n4;
                    const float* bp = Bm + (long)(kc * 32 + kr) * NCOL + col;
                    float4 v;
                    if (col + 4 <= NCOL) v = *(const float4*)bp;
                    else {
                        v.x = (col + 0 < NCOL) ? bp[0] : 0.f;
                        v.y = (col + 1 < NCOL) ? bp[1] : 0.f;
                        v.z = (col + 2 < NCOL) ? bp[2] : 0.f;
                        v.w = (col + 3 < NCOL) ? bp[3] : 0.f;
                    }
                    *(float4*)&Bs[kr * PITCH + n4] = v;
                }
            }
            __syncthreads();
            #pragma unroll
            for (int kk = 0; kk < 32; ++kk) {
                float4 a0 = *(const float4*)&As[kk * PITCH + ty * 8];
                float4 a1 = *(const float4*)&As[kk * PITCH + ty * 8 + 4];
                float4 b0 = *(const float4*)&Bs[kk * PITCH + tx * 8];
                float4 b1 = *(const float4*)&Bs[kk * PITCH + tx * 8 + 4];
                u64 ad[8] = {dup2(a0.x), dup2(a0.y), dup2(a0.z), dup2(a0.w),
                             dup2(a1.x), dup2(a1.y), dup2(a1.z), dup2(a1.w)};
                u64 bp4[4] = {pk2(b0.x, b0.y), pk2(b0.z, b0.w),
                              pk2(b1.x, b1.y), pk2(b1.z, b1.w)};
                #pragma unroll
                for (int i = 0; i < 8; ++i)
                    #pragma unroll
                    for (int j = 0; j < 4; ++j)
                        fma2(acc[i][j], ad[i], bp4[j]);
            }
            __syncthreads();
        }

        if (phase == 0) {
            // stash z1 + bias into Zs (same thread re-reads in phase 1)
            #pragma unroll
            for (int i = 0; i < 8; ++i) {
                int row = ty * 8 + i;
                float bv = bias[row];
                float c[8];
                #pragma unroll
                for (int j = 0; j < 4; ++j) un2(acc[i][j], c[2 * j], c[2 * j + 1]);
                float4 v0 = {c[0] + bv, c[1] + bv, c[2] + bv, c[3] + bv};
                float4 v1 = {c[4] + bv, c[5] + bv, c[6] + bv, c[7] + bv};
                *(float4*)&Zs[row * PITCH + tx * 8]     = v0;
                *(float4*)&Zs[row * PITCH + tx * 8 + 4] = v1;
            }
        } else {
            // GLU: g = z1 * sigmoid(z2); write G flat [(bb*128+o)*250 + l]
            #pragma unroll
            for (int i = 0; i < 8; ++i) {
                int o = ty * 8 + i;
                float bv = bias[128 + o];
                float c[8];
                #pragma unroll
                for (int j = 0; j < 4; ++j) un2(acc[i][j], c[2 * j], c[2 * j + 1]);
                #pragma unroll
                for (int j = 0; j < 8; ++j) {
                    long col = n0 + tx * 8 + j;
                    if (col < NCOL) {
                        float z1 = Zs[o * PITCH + tx * 8 + j];
                        float z2 = c[j] + bv;
                        float g = z1 / (1.f + expf(-z2));
                        int bb = (int)(col / 250);
                        int l  = (int)(col - (long)bb * 250);
                        g_buf0[((long)bb * 128 + o) * 250 + l] = g;
                    }
                }
            }
        }
        __syncthreads();
    }
}

// ---------------------------------------------------------------------------
// GEMM2 (lw) on flat rows: C[r][c] = sum_k G[r][k] * W[c][k] + lb[c]
__global__ void __launch_bounds__(256, 2)
gemm_lw(const float* __restrict__ W, const float* __restrict__ bias) {
    const float* __restrict__ G = g_buf0;
    float* __restrict__ C = g_buf1;
    __shared__ float Gs[32 * PITCH];
    __shared__ float Ws[32 * PITCH];

    int tid = threadIdx.x;
    int tx = tid & 15, ty = tid >> 4;
    long r0 = (long)blockIdx.x * 128;

    u64 acc[8][4];
    #pragma unroll
    for (int i = 0; i < 8; ++i)
        #pragma unroll
        for (int j = 0; j < 4; ++j) acc[i][j] = 0ull;

    for (int kc = 0; kc < 4; ++kc) {
        int c4 = (tid & 7) * 4;
        int rb = tid >> 3;
        #pragma unroll
        for (int p = 0; p < 4; ++p) {
            int r = rb + p * 32;
            long grow = r0 + r;
            if (grow >= NCOL) grow = NCOL - 1;   // clamp; stores guarded
            float4 v = *(const float4*)(G + grow * 128 + kc * 32 + c4);
            Gs[(c4 + 0) * PITCH + r] = v.x; Gs[(c4 + 1) * PITCH + r] = v.y;
            Gs[(c4 + 2) * PITCH + r] = v.z; Gs[(c4 + 3) * PITCH + r] = v.w;
            float4 wv = *(const float4*)(W + (long)r * 128 + kc * 32 + c4);
            Ws[(c4 + 0) * PITCH + r] = wv.x; Ws[(c4 + 1) * PITCH + r] = wv.y;
            Ws[(c4 + 2) * PITCH + r] = wv.z; Ws[(c4 + 3) * PITCH + r] = wv.w;
        }
        __syncthreads();
        #pragma unroll
        for (int kk = 0; kk < 32; ++kk) {
            float4 a0 = *(const float4*)&Gs[kk * PITCH + ty * 8];
            float4 a1 = *(const float4*)&Gs[kk * PITCH + ty * 8 + 4];
            float4 b0 = *(const float4*)&Ws[kk * PITCH + tx * 8];
            float4 b1 = *(const float4*)&Ws[kk * PITCH + tx * 8 + 4];
            u64 ad[8] = {dup2(a0.x), dup2(a0.y), dup2(a0.z), dup2(a0.w),
                         dup2(a1.x), dup2(a1.y), dup2(a1.z), dup2(a1.w)};
            u64 bp4[4] = {pk2(b0.x, b0.y), pk2(b0.z, b0.w),
                          pk2(b1.x, b1.y), pk2(b1.z, b1.w)};
            #pragma unroll
            for (int i = 0; i < 8; ++i)
                #pragma unroll
                for (int j = 0; j < 4; ++j)
                    fma2(acc[i][j], ad[i], bp4[j]);
        }
        __syncthreads();
    }
    float bb0[8];
    {
        float4 b0 = *(const float4*)(bias + tx * 8);
        float4 b1 = *(const float4*)(bias + tx * 8 + 4);
        bb0[0] = b0.x; bb0[1] = b0.y; bb0[2] = b0.z; bb0[3] = b0.w;
        bb0[4] = b1.x; bb0[5] = b1.y; bb0[6] = b1.z; bb0[7] = b1.w;
    }
    #pragma unroll
    for (int i = 0; i < 8; ++i) {
        long row = r0 + ty * 8 + i;
        if (row >= NCOL) continue;
        float c[8];
        #pragma unroll
        for (int j = 0; j < 4; ++j) un2(acc[i][j], c[2 * j], c[2 * j + 1]);
        float4 v0 = {c[0] + bb0[0], c[1] + bb0[1], c[2] + bb0[2], c[3] + bb0[3]};
        float4 v1 = {c[4] + bb0[4], c[5] + bb0[5], c[6] + bb0[6], c[7] + bb0[7]};
        float* cp = C + row * 128 + tx * 8;
        *(float4*)(cp) = v0;
        *(float4*)(cp + 4) = v1;
    }
}

// ---------------------------------------------------------------------------
__global__ void zero_stats() {
    if (threadIdx.x < 8) g_stats[threadIdx.x] = 0.0;
}

// intra: pre[b][n][k][s] = Lf[(b*250+s)*32000 + n*250 + k]; tiled transpose + stats
__global__ void trans_stats_intra() {
    __shared__ float tile[32][33];
    __shared__ float rs[32], rq[32];
    int bn = blockIdx.y;
    int b = bn >> 7, n = bn & 127;
    int tk = blockIdx.x & 7, ts = blockIdx.x >> 3;
    int s = ts * 32 + threadIdx.y;
    int k = tk * 32 + threadIdx.x;
    float v = 0.f;
    if (s < 250 && k < 250)
        v = g_buf1[((long)(b * 250 + s)) * 32000 + n * 250 + k];
    tile[threadIdx.y][threadIdx.x] = v;
    __syncthreads();
    int k2 = tk * 32 + threadIdx.y;
    int s2 = ts * 32 + threadIdx.x;
    float wv = tile[threadIdx.x][threadIdx.y];
    bool ok = (k2 < 250 && s2 < 250);
    if (ok)
        g_buf2[(((long)bn * 250 + k2) * 250) + s2] = wv;
    float sum = ok ? wv : 0.f;
    float sq = sum * sum;
    #pragma unroll
    for (int off = 16; off; off >>= 1) {
        sum += __shfl_down_sync(0xffffffffu, sum, off);
        sq  += __shfl_down_sync(0xffffffffu, sq, off);
    }
    if (threadIdx.x == 0) { rs[threadIdx.y] = sum; rq[threadIdx.y] = sq; }
    __syncthreads();
    if (threadIdx.y == 0) {
        float a = rs[threadIdx.x], q = rq[threadIdx.x];
        #pragma unroll
        for (int off = 16; off; off >>= 1) {
            a += __shfl_down_sync(0xffffffffu, a, off);
            q += __shfl_down_sync(0xffffffffu, q, off);
        }
        if (threadIdx.x == 0) {
            atomicAdd(&g_stats[2 * b], (double)a);
            atomicAdd(&g_stats[2 * b + 1], (double)q);
        }
    }
}

// inter: pre[b][n][k][s] = Lf[(b*250+k)*32000 + n*250 + s]; coalesced copy + stats
__global__ void copy_stats_inter() {
    int i = blockIdx.x * 256 + threadIdx.x;
    int s = i % 250;
    int t = i / 250;
    int k = t % 250; t /= 250;
    int n = t & 127;
    int b = t >> 7;
    float v = g_buf1[((long)(b * 250 + k)) * 32000 + n * 250 + s];
    g_buf2[i] = v;
    float sum = v, sq = v * v;
    #pragma unroll
    for (int off = 16; off; off >>= 1) {
        sum += __shfl_down_sync(0xffffffffu, sum, off);
        sq  += __shfl_down_sync(0xffffffffu, sq, off);
    }
    __shared__ float ssum[8], ssq[8];
    int lane = threadIdx.x & 31, w = threadIdx.x >> 5;
    if (lane == 0) { ssum[w] = sum; ssq[w] = sq; }
    __syncthreads();
    if (threadIdx.x == 0) {
        float a = 0.f, q = 0.f;
        #pragma unroll
        for (int j = 0; j < 8; ++j) { a += ssum[j]; q += ssq[j]; }
        atomicAdd(&g_stats[2 * b], (double)a);
        atomicAdd(&g_stats[2 * b + 1], (double)q);
    }
}

// GroupNorm apply + residual; intra version also emits inter-path u (fused pack)
__global__ void norm_intra(const float* __restrict__ gg, const float* __restrict__ gb,
                           const float* __restrict__ x, float* __restrict__ out) {
    int i = blockIdx.x * 256 + threadIdx.x;
    int s = i % 250;
    int t = i / 250;
    int k = t % 250; t /= 250;
    int n = t & 127;
    int b = t >> 7;
    double mu  = g_stats[2 * b] / (double)PERB;
    double var = g_stats[2 * b + 1] / (double)PERB - mu * mu;
    float inv = (float)(1.0 / sqrt(var + 1e-8));
    float val = (g_buf2[i] - (float)mu) * inv * gg[n] + gb[n] + x[i];
    out[i] = val;
    g_buf0[(((long)(b * 250 + k)) * 128 + n) * 250 + s] = val;
}

__global__ void norm_final(const float* __restrict__ gg, const float* __restrict__ gb,
                           float* __restrict__ out) {
    int i = blockIdx.x * 256 + threadIdx.x;
    int n = (i / 62500) & 127;
    int b = i / PERB;
    double mu  = g_stats[2 * b] / (double)PERB;
    double var = g_stats[2 * b + 1] / (double)PERB - mu * mu;
    float inv = (float)(1.0 / sqrt(var + 1e-8));
    out[i] = (g_buf2[i] - (float)mu) * inv * gg[n] + gb[n] + out[i];
}

// ---------------------------------------------------------------------------
extern "C" void kernel_launch(void* const* d_in, const int* in_sizes, int n_in,
                              void* d_out, int out_size) {
    const float* x = (const float*)d_in[0];
    const float* ip[12];
    const float* pp[12];
    for (int j = 0; j < 12; ++j) ip[j] = (const float*)d_in[1 + j];
    for (int j = 0; j < 12; ++j) pp[j] = (const float*)d_in[13 + j];
    float* out = (float*)d_out;

    const int EB = TOT / 256;
    const int SMEM_OWGLU = (64 * PITCH + 128 * PITCH) * sizeof(float);  // ~99KB
    cudaFuncSetAttribute(gemm_ow_glu, cudaFuncAttributeMaxDynamicSharedMemorySize, SMEM_OWGLU);

    // ---- intra path ----
    pack_intra<<<dim3(64, 512), dim3(32, 32)>>>(x);
    kern_compute<<<NC, 256>>>(ip[0], ip[1], ip[2], ip[3], ip[4]);
    conv_gelu2<<<dim3(16, 1000), 256>>>(ip[5]);
    gemm_ow_glu<<<1954, 256, SMEM_OWGLU>>>(ip[6], ip[7]);
    gemm_lw<<<1954, 256>>>(ip[8], ip[9]);
    zero_stats<<<1, 32>>>();
    trans_stats_intra<<<dim3(64, 512), dim3(32, 32)>>>();
    norm_intra<<<EB, 256>>>(ip[10], ip[11], x, out);

    // ---- inter path ----
    kern_compute<<<NC, 256>>>(pp[0], pp[1], pp[2], pp[3], pp[4]);
    conv_gelu2<<<dim3(16, 1000), 256>>>(pp[5]);
    gemm_ow_glu<<<1954, 256, SMEM_OWGLU>>>(pp[6], pp[7]);
    gemm_lw<<<1954, 256>>>(pp[8], pp[9]);
    zero_stats<<<1, 32>>>();
    copy_stats_inter<<<EB, 256>>>();
    norm_final<<<EB, 256>>>(pp[10], pp[11], out);
}